// round 8
// baseline (speedup 1.0000x reference)
#include <cuda_runtime.h>
#include <math.h>

#define Bv 64
#define Tv 1024
#define Hv 512
#define NCTA 128

// ---------------- device scratch ----------------
__device__ float g_Xr[(size_t)Tv * Bv * Hv];   // pre-projected r inputs [m][j], m=t*64+b
__device__ float g_Xz[(size_t)Tv * Bv * Hv];
__device__ float g_Xh[(size_t)Tv * Bv * Hv];
__device__ float g_HS[(size_t)Tv * Bv * Hv];   // layer-0 hidden outputs
__device__ float g_pA[8  * Bv * 1024];         // split-K partials: rz GEMM
__device__ float g_pB[16 * Bv * Hv];           // split-K partials: h~ GEMM
__device__ float g_h [Bv * Hv];                // current hidden state
__device__ unsigned int g_arrive[NCTA * 32];   // one 128B line per CTA
__device__ unsigned int g_go;                  // broadcast go-epoch

__global__ void reset_bar() {
    int i = blockIdx.x * blockDim.x + threadIdx.x;
    if (i < NCTA * 32) g_arrive[i] = 0u;
    if (i == 0) g_go = 0u;
}

// Distributed-flag grid barrier: arrivals on distinct cache lines (no atomic
// contention), CTA0 aggregates with 127 parallel pollers, single release store
// to a read-shared go-word. Release->acquire chain carries data visibility.
__device__ __forceinline__ void gbar(int cid, unsigned int &epoch) {
    epoch++;
    __syncthreads();
    if (cid == 0) {
        if (threadIdx.x > 0 && threadIdx.x < NCTA) {
            unsigned int v;
            for (;;) {
                asm volatile("ld.acquire.gpu.global.u32 %0, [%1];"
                             : "=r"(v) : "l"(&g_arrive[threadIdx.x * 32]));
                if (v >= epoch) break;
                __nanosleep(40);
            }
        }
        __syncthreads();
        if (threadIdx.x == 0)
            asm volatile("st.release.gpu.global.u32 [%0], %1;"
                         :: "l"(&g_go), "r"(epoch));
        __syncthreads();
    } else {
        if (threadIdx.x == 0) {
            asm volatile("st.release.gpu.global.u32 [%0], %1;"
                         :: "l"(&g_arrive[cid * 32]), "r"(epoch));
            unsigned int v;
            for (;;) {
                asm volatile("ld.acquire.gpu.global.u32 %0, [%1];"
                             : "=r"(v) : "l"(&g_go));
                if (v >= epoch) break;
                __nanosleep(40);
            }
        }
        __syncthreads();
    }
}

// ---------------- pre-projection GEMM (128x64 tile, 8x4 micro-tile) ----------------
// For all m in [0,65536), j in [0,1536):
//   j<512  : g_Xr[m][j]      = sum_k A[m][k]*Wr[j][k]      + br[j]
//   j<1024 : g_Xz[m][j-512]  = sum_k A[m][k]*Wz[j-512][k]  + bz[..]
//   else   : g_Xh[m][j-1024] = sum_k A[m][k]*Wh[j-1024][k] + bh[..]
// GATHER=1: A[m] = emb[tokens[b*T+t]] (t=m>>6, b=m&63);  GATHER=0: A = g_HS.
template <int GATHER>
__global__ void __launch_bounds__(256) xproj_kernel(
    const float *__restrict__ emb, const int *__restrict__ tokens,
    const float *__restrict__ Wr, const float *__restrict__ Wz,
    const float *__restrict__ Wh,
    const float *__restrict__ br, const float *__restrict__ bz,
    const float *__restrict__ bh,
    int K, int ldW)
{
    __shared__ __align__(16) float As[16][132];
    __shared__ __align__(16) float Bs[16][68];
    __shared__ const float *rowp[128];
    __shared__ const float *colp[64];

    const int tid = threadIdx.x;
    const int m0 = blockIdx.x * 128;
    const int j0 = blockIdx.y * 64;

    if (tid < 128) {
        int m = m0 + tid;
        if (GATHER) {
            int b = m & 63, t = m >> 6;
            rowp[tid] = emb + (size_t)tokens[b * Tv + t] * 256;
        } else {
            rowp[tid] = g_HS + (size_t)m * Hv;
        }
    } else if (tid < 192) {
        int j = j0 + tid - 128;
        const float *w;
        if (j < 512)       w = Wr + (size_t)j * ldW;
        else if (j < 1024) w = Wz + (size_t)(j - 512) * ldW;
        else               w = Wh + (size_t)(j - 1024) * ldW;
        colp[tid - 128] = w;
    }
    __syncthreads();

    const int tx = tid & 15, ty = tid >> 4;
    float acc[8][4];
#pragma unroll
    for (int i = 0; i < 8; i++)
#pragma unroll
        for (int j = 0; j < 4; j++) acc[i][j] = 0.0f;

    for (int k0 = 0; k0 < K; k0 += 16) {
#pragma unroll
        for (int i = 0; i < 2; i++) {              // A tile: 128 m x 16 k
            int id = tid + i * 256;
            int kk = id & 3, r = id >> 2;
            float4 v = *(const float4 *)(rowp[r] + k0 + kk * 4);
            As[kk * 4 + 0][r] = v.x; As[kk * 4 + 1][r] = v.y;
            As[kk * 4 + 2][r] = v.z; As[kk * 4 + 3][r] = v.w;
        }
        {                                          // B tile: 64 j x 16 k
            int kk = tid & 3, jj = tid >> 2;
            float4 v = *(const float4 *)(colp[jj] + k0 + kk * 4);
            Bs[kk * 4 + 0][jj] = v.x; Bs[kk * 4 + 1][jj] = v.y;
            Bs[kk * 4 + 2][jj] = v.z; Bs[kk * 4 + 3][jj] = v.w;
        }
        __syncthreads();
#pragma unroll
        for (int k = 0; k < 16; k++) {
            float a[8], w[4];
            *(float4 *)&a[0] = *(const float4 *)&As[k][ty * 8];
            *(float4 *)&a[4] = *(const float4 *)&As[k][ty * 8 + 4];
            *(float4 *)&w[0] = *(const float4 *)&Bs[k][tx * 4];
#pragma unroll
            for (int i = 0; i < 8; i++)
#pragma unroll
                for (int j = 0; j < 4; j++)
                    acc[i][j] = fmaf(a[i], w[j], acc[i][j]);
        }
        __syncthreads();
    }

    float *dst; const float *bias; int jloc;
    if (j0 < 512)       { dst = g_Xr; bias = br; jloc = j0; }
    else if (j0 < 1024) { dst = g_Xz; bias = bz; jloc = j0 - 512; }
    else                { dst = g_Xh; bias = bh; jloc = j0 - 1024; }
    const int c0 = jloc + tx * 4;
    const float b0 = bias[c0], b1 = bias[c0 + 1], b2 = bias[c0 + 2], b3 = bias[c0 + 3];
#pragma unroll
    for (int i = 0; i < 8; i++) {
        int m = m0 + ty * 8 + i;
        float4 v = make_float4(acc[i][0] + b0, acc[i][1] + b1,
                               acc[i][2] + b2, acc[i][3] + b3);
        *(float4 *)&dst[(size_t)m * Hv + c0] = v;
    }
}

// ---------------- persistent GRU recurrence ----------------
// 128 CTAs x 256 threads, all co-resident. 3 grid barriers per time step.
// Phase A: pA[kb][b][col1024] partial of h @ [Wr_h;Wz_h]^T  (kb: 8 k-blocks of 64)
// Phase B: rh = sigmoid(xr + sum pA) * h  staged per k-chunk, then
//          pB[kb2][b][col512] partial of rh @ Wh_h^T        (kb2: 16 k-blocks of 32)
// Phase C: z = sigmoid(xz + sum pA[.,512+j]); h' = h + z*(tanh(xh + sum pB) - h)
__global__ void __launch_bounds__(256) gru_rec_kernel(
    const float *__restrict__ Wr, const float *__restrict__ Wz,
    const float *__restrict__ Wh,
    int D, int ldW, int store_hs)
{
    __shared__ __align__(16) float Wa[64 * 68];
    __shared__ __align__(16) float Wb[32 * 68];
    __shared__ __align__(16) float Sa[64 * 68];

    const int tid = threadIdx.x;
    const int cid = blockIdx.x;
    const int tx = tid & 15, ty = tid >> 4;
    const int nb = cid & 15, kb = cid >> 4;     // phase A role
    const int nb2 = cid & 7, kb2 = cid >> 3;    // phase B role

    // Preload recurrent weight slices once (h-part = columns [D, D+512)).
    for (int e = tid; e < 64 * 64; e += 256) {
        int k = e & 63, j = e >> 6;
        int jg = nb * 64 + j;
        const float *w = (jg < 512) ? (Wr + (size_t)jg * ldW)
                                    : (Wz + (size_t)(jg - 512) * ldW);
        Wa[k * 68 + j] = w[D + kb * 64 + k];
    }
    for (int e = tid; e < 32 * 64; e += 256) {
        int k = e & 31, j = e >> 5;
        Wb[k * 68 + j] = Wh[(size_t)(nb2 * 64 + j) * ldW + D + kb2 * 32 + k];
    }
    __stcg(&g_h[cid * 256 + tid], 0.0f);   // h0 = 0

    unsigned int epoch = 0;
    gbar(cid, epoch);

    for (int t = 0; t < Tv; t++) {
        const size_t xb = (size_t)t * Bv * Hv;

        // ---- Phase A: stage h[:, kb*64..+64) into Sa[k][b], then 64x64x64 GEMM
        for (int e = tid; e < 64 * 16; e += 256) {
            int kq = e & 15, b = e >> 4;
            float4 v = __ldcg((const float4 *)&g_h[b * Hv + kb * 64 + kq * 4]);
            Sa[(kq * 4 + 0) * 68 + b] = v.x; Sa[(kq * 4 + 1) * 68 + b] = v.y;
            Sa[(kq * 4 + 2) * 68 + b] = v.z; Sa[(kq * 4 + 3) * 68 + b] = v.w;
        }
        __syncthreads();
        {
            float acc[4][4];
#pragma unroll
            for (int i = 0; i < 4; i++)
#pragma unroll
                for (int j = 0; j < 4; j++) acc[i][j] = 0.0f;
#pragma unroll 8
            for (int k = 0; k < 64; k++) {
                float a[4], w[4];
                *(float4 *)a = *(const float4 *)&Sa[k * 68 + ty * 4];
                *(float4 *)w = *(const float4 *)&Wa[k * 68 + tx * 4];
#pragma unroll
                for (int i = 0; i < 4; i++)
#pragma unroll
                    for (int j = 0; j < 4; j++)
                        acc[i][j] = fmaf(a[i], w[j], acc[i][j]);
            }
#pragma unroll
            for (int i = 0; i < 4; i++) {
                int b = ty * 4 + i;
                float4 v = make_float4(acc[i][0], acc[i][1], acc[i][2], acc[i][3]);
                __stcg((float4 *)&g_pA[((size_t)kb * 64 + b) * 1024 + nb * 64 + tx * 4], v);
            }
        }
        gbar(cid, epoch);

        // ---- Phase B: stage rh[k][b] for k-chunk kb2, then 64x64x32 GEMM
        for (int e = tid; e < 32 * 64; e += 256) {
            int k = e & 31, b = e >> 5;
            int kg = kb2 * 32 + k;
            float s = g_Xr[xb + (size_t)b * Hv + kg];
#pragma unroll
            for (int p = 0; p < 8; p++)
                s += __ldcg(&g_pA[((size_t)p * 64 + b) * 1024 + kg]);
            float rg = 1.0f / (1.0f + expf(-s));
            Sa[k * 68 + b] = rg * __ldcg(&g_h[b * Hv + kg]);
        }
        __syncthreads();
        {
            float acc[4][4];
#pragma unroll
            for (int i = 0; i < 4; i++)
#pragma unroll
                for (int j = 0; j < 4; j++) acc[i][j] = 0.0f;
#pragma unroll 8
            for (int k = 0; k < 32; k++) {
                float a[4], w[4];
                *(float4 *)a = *(const float4 *)&Sa[k * 68 + ty * 4];
                *(float4 *)w = *(const float4 *)&Wb[k * 68 + tx * 4];
#pragma unroll
                for (int i = 0; i < 4; i++)
#pragma unroll
                    for (int j = 0; j < 4; j++)
                        acc[i][j] = fmaf(a[i], w[j], acc[i][j]);
            }
#pragma unroll
            for (int i = 0; i < 4; i++) {
                int b = ty * 4 + i;
                float4 v = make_float4(acc[i][0], acc[i][1], acc[i][2], acc[i][3]);
                __stcg((float4 *)&g_pB[((size_t)kb2 * 64 + b) * Hv + nb2 * 64 + tx * 4], v);
            }
        }
        gbar(cid, epoch);

        // ---- Phase C: h update (1 element per thread)
        {
            int e = cid * 256 + tid;          // [0, 32768)
            int b = e >> 9, j = e & 511;
            float sz = g_Xz[xb + (size_t)b * Hv + j];
#pragma unroll
            for (int p = 0; p < 8; p++)
                sz += __ldcg(&g_pA[((size_t)p * 64 + b) * 1024 + 512 + j]);
            float sh = g_Xh[xb + (size_t)b * Hv + j];
#pragma unroll
            for (int p = 0; p < 16; p++)
                sh += __ldcg(&g_pB[((size_t)p * 64 + b) * Hv + j]);
            float h = __ldcg(&g_h[b * Hv + j]);
            float z = 1.0f / (1.0f + expf(-sz));
            float hn = h + z * (tanhf(sh) - h);
            __stcg(&g_h[b * Hv + j], hn);
            if (store_hs)
                g_HS[(size_t)(t * Bv + b) * Hv + j] = hn;
        }
        gbar(cid, epoch);
    }
}

// ---------------- final FC: out[b][c] = h_last[b] . fcW[c] + fcb[c] ----------------
__global__ void fc_kernel(const float *__restrict__ fcW,
                          const float *__restrict__ fcb,
                          float *__restrict__ out)
{
    int b = threadIdx.x >> 1, c = threadIdx.x & 1;
    float s = 0.0f;
    for (int j = 0; j < Hv; j += 4) {
        float4 hv = *(const float4 *)&g_h[b * Hv + j];
        float4 wv = *(const float4 *)&fcW[c * Hv + j];
        s = fmaf(hv.x, wv.x, s); s = fmaf(hv.y, wv.y, s);
        s = fmaf(hv.z, wv.z, s); s = fmaf(hv.w, wv.w, s);
    }
    out[b * 2 + c] = s + fcb[c];
}

// ---------------- launch ----------------
extern "C" void kernel_launch(void* const* d_in, const int* in_sizes, int n_in,
                              void* d_out, int out_size) {
    const int   *tokens = (const int *)d_in[0];
    const float *emb = (const float *)d_in[1];
    const float *Wr0 = (const float *)d_in[2];
    const float *br0 = (const float *)d_in[3];
    const float *Wz0 = (const float *)d_in[4];
    const float *bz0 = (const float *)d_in[5];
    const float *Wh0 = (const float *)d_in[6];
    const float *bh0 = (const float *)d_in[7];
    const float *Wr1 = (const float *)d_in[8];
    const float *br1 = (const float *)d_in[9];
    const float *Wz1 = (const float *)d_in[10];
    const float *bz1 = (const float *)d_in[11];
    const float *Wh1 = (const float *)d_in[12];
    const float *bh1 = (const float *)d_in[13];
    const float *fcW = (const float *)d_in[14];
    const float *fcb = (const float *)d_in[15];
    float *out = (float *)d_out;

    dim3 gx(512, 24);

    // Layer 0
    xproj_kernel<1><<<gx, 256>>>(emb, tokens, Wr0, Wz0, Wh0, br0, bz0, bh0,
                                 256, 768);
    reset_bar<<<16, 256>>>();
    gru_rec_kernel<<<NCTA, 256>>>(Wr0, Wz0, Wh0, 256, 768, 1);

    // Layer 1
    xproj_kernel<0><<<gx, 256>>>(nullptr, nullptr, Wr1, Wz1, Wh1, br1, bz1, bh1,
                                 512, 1024);
    reset_bar<<<16, 256>>>();
    gru_rec_kernel<<<NCTA, 256>>>(Wr1, Wz1, Wh1, 512, 1024, 0);

    // Classifier
    fc_kernel<<<1, 128>>>(fcW, fcb, out);
}

// round 9
// speedup vs baseline: 1.4098x; 1.4098x over previous
#include <cuda_runtime.h>
#include <math.h>

#define Bv 64
#define Tv 1024
#define Hv 512
#define NCTA 128

// ---------------- device scratch ----------------
// X projections stored TRANSPOSED: X?T[t][j][b] = [(t*512 + j)*64 + b]
__device__ __align__(16) float g_XrT[(size_t)Tv * Hv * Bv];
__device__ __align__(16) float g_XzT[(size_t)Tv * Hv * Bv];
__device__ __align__(16) float g_XhT[(size_t)Tv * Hv * Bv];
__device__ __align__(16) float g_HS [(size_t)Tv * Bv * Hv];  // layer-0 outputs [m][j]
__device__ __align__(16) float g_hT [Hv * Bv];               // hidden state [j][b]
__device__ __align__(16) float g_rhT[Hv * Bv];               // r*h [j][b]
__device__ __align__(16) float g_z  [Hv * Bv];               // z gate [j][b]
__device__ unsigned int g_bar;

__global__ void reset_bar() { g_bar = 0u; }

// R7-proven atomic-counter grid barrier.
__device__ __forceinline__ void gbar(unsigned int &target) {
    __syncthreads();
    if (threadIdx.x == 0) {
        __threadfence();
        atomicAdd(&g_bar, 1u);
        target += NCTA;
        while (*(volatile unsigned int *)&g_bar < target) { }
        __threadfence();
    }
    __syncthreads();
}

// Packed fp32x2 helpers (Blackwell FFMA2 via PTX)
#define FMA2(d, a, b) asm("fma.rn.f32x2 %0, %1, %2, %0;" : "+l"(d) : "l"(a), "l"(b))
#define ADD2(d, a)    asm("add.rn.f32x2 %0, %0, %1;"     : "+l"(d) : "l"(a))
#define CP16(dst, src) asm volatile("cp.async.cg.shared.global [%0], [%1], 16;" \
                                    :: "r"(dst), "l"(src))

// ---------------- pre-projection GEMM (128x64 tile, 8x4 micro) ----------------
// Writes transposed: j<512 -> g_XrT, j<1024 -> g_XzT, else -> g_XhT.
template <int GATHER>
__global__ void __launch_bounds__(256) xproj_kernel(
    const float *__restrict__ emb, const int *__restrict__ tokens,
    const float *__restrict__ Wr, const float *__restrict__ Wz,
    const float *__restrict__ Wh,
    const float *__restrict__ br, const float *__restrict__ bz,
    const float *__restrict__ bh,
    int K, int ldW)
{
    __shared__ __align__(16) float As[16][132];
    __shared__ __align__(16) float Bs[16][68];
    __shared__ const float *rowp[128];
    __shared__ const float *colp[64];

    const int tid = threadIdx.x;
    const int m0 = blockIdx.x * 128;
    const int j0 = blockIdx.y * 64;

    if (tid < 128) {
        int m = m0 + tid;
        if (GATHER) {
            int b = m & 63, t = m >> 6;
            rowp[tid] = emb + (size_t)tokens[b * Tv + t] * 256;
        } else {
            rowp[tid] = g_HS + (size_t)m * Hv;
        }
    } else if (tid < 192) {
        int j = j0 + tid - 128;
        const float *w;
        if (j < 512)       w = Wr + (size_t)j * ldW;
        else if (j < 1024) w = Wz + (size_t)(j - 512) * ldW;
        else               w = Wh + (size_t)(j - 1024) * ldW;
        colp[tid - 128] = w;
    }
    __syncthreads();

    const int tx = tid & 15, ty = tid >> 4;
    float acc[8][4];
#pragma unroll
    for (int i = 0; i < 8; i++)
#pragma unroll
        for (int j = 0; j < 4; j++) acc[i][j] = 0.0f;

    for (int k0 = 0; k0 < K; k0 += 16) {
#pragma unroll
        for (int i = 0; i < 2; i++) {
            int id = tid + i * 256;
            int kk = id & 3, r = id >> 2;
            float4 v = *(const float4 *)(rowp[r] + k0 + kk * 4);
            As[kk * 4 + 0][r] = v.x; As[kk * 4 + 1][r] = v.y;
            As[kk * 4 + 2][r] = v.z; As[kk * 4 + 3][r] = v.w;
        }
        {
            int kk = tid & 3, jj = tid >> 2;
            float4 v = *(const float4 *)(colp[jj] + k0 + kk * 4);
            Bs[kk * 4 + 0][jj] = v.x; Bs[kk * 4 + 1][jj] = v.y;
            Bs[kk * 4 + 2][jj] = v.z; Bs[kk * 4 + 3][jj] = v.w;
        }
        __syncthreads();
#pragma unroll
        for (int k = 0; k < 16; k++) {
            float a[8], w[4];
            *(float4 *)&a[0] = *(const float4 *)&As[k][ty * 8];
            *(float4 *)&a[4] = *(const float4 *)&As[k][ty * 8 + 4];
            *(float4 *)&w[0] = *(const float4 *)&Bs[k][tx * 4];
#pragma unroll
            for (int i = 0; i < 8; i++)
#pragma unroll
                for (int j = 0; j < 4; j++)
                    acc[i][j] = fmaf(a[i], w[j], acc[i][j]);
        }
        __syncthreads();
    }

    float *dst; const float *bias; int jloc;
    if (j0 < 512)       { dst = g_XrT; bias = br; jloc = j0; }
    else if (j0 < 1024) { dst = g_XzT; bias = bz; jloc = j0 - 512; }
    else                { dst = g_XhT; bias = bh; jloc = j0 - 1024; }

    const int c0 = jloc + tx * 4;
    const float bs0 = bias[c0], bs1 = bias[c0 + 1], bs2 = bias[c0 + 2], bs3 = bias[c0 + 3];
    const int t  = (m0 >> 6) + (ty >> 3);
    const int b0 = (ty & 7) * 8;
    const float bsv[4] = {bs0, bs1, bs2, bs3};
#pragma unroll
    for (int jj = 0; jj < 4; jj++) {
        int jg = c0 + jj;
        float4 lo = make_float4(acc[0][jj] + bsv[jj], acc[1][jj] + bsv[jj],
                                acc[2][jj] + bsv[jj], acc[3][jj] + bsv[jj]);
        float4 hi = make_float4(acc[4][jj] + bsv[jj], acc[5][jj] + bsv[jj],
                                acc[6][jj] + bsv[jj], acc[7][jj] + bsv[jj]);
        size_t o = ((size_t)t * 512 + jg) * 64 + b0;
        *(float4 *)&dst[o]     = lo;
        *(float4 *)&dst[o + 4] = hi;
    }
}

// ---------------- persistent GRU recurrence (2 barriers/step) ----------------
// SMEM layout (floats):
//   W1d [0, 8192)          : phase-1 weights, dup pairs  (8 cols x 512 k x 2)
//   W2d [8192, 12288)      : phase-2 weights, dup pairs  (4 cols x 512 k x 2)
//   HST [12288, 45056)     : staging for h / rh, [k][b], full 512x64
//   SRED(bytes 180224..)   : 256 threads x 4 u64
//   SOUT(floats 47104..)   : 8 x 64
#define SM_W1   0
#define SM_W2   8192
#define SM_HST  12288
#define SM_SRED 45056          /* float index; 8B aligned (45056*4 % 8 == 0) */
#define SM_SOUT 47104
#define SM_TOT_FLOATS 47616    /* 190464 bytes */

__global__ void __launch_bounds__(256) gru_rec_kernel(
    const float *__restrict__ Wr, const float *__restrict__ Wz,
    const float *__restrict__ Wh,
    int D, int ldW, int store_hs)
{
    extern __shared__ __align__(16) float smem[];
    float *w1d = smem + SM_W1;
    float *w2d = smem + SM_W2;
    float *hst = smem + SM_HST;
    unsigned long long *sred = (unsigned long long *)(smem + SM_SRED);
    float *sout = smem + SM_SOUT;

    const int tid = threadIdx.x;
    const int cid = blockIdx.x;
    const int JA0 = cid * 8;   // phase-1 rz-column base (0..1023)
    const int JB0 = cid * 4;   // phase-2 h-column base  (0..511)

    // ---- one-time preload of recurrent weight slices (dup-packed) ----
    for (int e = tid; e < 4096; e += 256) {        // e = jl*512 + k
        int jl = e >> 9, k = e & 511;
        int jg = JA0 + jl;
        const float *row = (jg < 512) ? (Wr + (size_t)jg * ldW)
                                      : (Wz + (size_t)(jg - 512) * ldW);
        float w = row[D + k];
        w1d[(k * 8 + jl) * 2]     = w;
        w1d[(k * 8 + jl) * 2 + 1] = w;
    }
    for (int e = tid; e < 2048; e += 256) {        // e = jl*512 + k
        int jl = e >> 9, k = e & 511;
        float w = Wh[(size_t)(JB0 + jl) * ldW + D + k];
        w2d[(k * 4 + jl) * 2]     = w;
        w2d[(k * 4 + jl) * 2 + 1] = w;
    }
    __stcg(&g_hT[cid * 256 + tid], 0.0f);          // h0 = 0
    unsigned int target = 0;
    gbar(target);

    const int bg1 = tid & 15, jg1 = (tid >> 4) & 3, ks1 = tid >> 6;   // phase 1
    const int bg2 = tid & 15, jg2 = (tid >> 4) & 1, ks2 = tid >> 5;   // phase 2

    for (int t = 0; t < Tv; t++) {
        const size_t xoff = (size_t)t * 32768;     // t*512*64

        // ================= PHASE 1: rz = h @ W1^T =================
        {
            // stage full g_hT into HST via 2 cp.async mega-chunks (64KB each)
#pragma unroll
            for (int half = 0; half < 2; half++) {
                const float *s = g_hT + half * 16384;
                unsigned db = (unsigned)__cvta_generic_to_shared(hst + half * 16384);
#pragma unroll
                for (int q = 0; q < 16; q++)
                    CP16(db + (tid + q * 256) * 16, s + (tid + q * 256) * 4);
                asm volatile("cp.async.commit_group;");
            }
            unsigned long long a0 = 0, a1 = 0, a2 = 0, a3 = 0;
#pragma unroll
            for (int half = 0; half < 2; half++) {
                if (half == 0) asm volatile("cp.async.wait_group 1;");
                else           asm volatile("cp.async.wait_group 0;");
                __syncthreads();
                const float *hp = hst + half * 16384 + (ks1 * 64) * 64 + bg1 * 4;
                const float *wp = w1d + ((half * 256 + ks1 * 64) * 8 + jg1 * 2) * 2;
#pragma unroll 4
                for (int kk = 0; kk < 64; kk++) {
                    ulonglong2 hv = *(const ulonglong2 *)hp;
                    ulonglong2 wv = *(const ulonglong2 *)wp;
                    FMA2(a0, hv.x, wv.x);
                    FMA2(a1, hv.y, wv.x);
                    FMA2(a2, hv.x, wv.y);
                    FMA2(a3, hv.y, wv.y);
                    hp += 64; wp += 16;
                }
                __syncthreads();   // protect hst before (none) / uniform
            }
            // intra-CTA k-split reduction (4-way)
            sred[tid * 4 + 0] = a0; sred[tid * 4 + 1] = a1;
            sred[tid * 4 + 2] = a2; sred[tid * 4 + 3] = a3;
            __syncthreads();
            if (tid < 64) {
#pragma unroll
                for (int s = 1; s < 4; s++) {
                    ADD2(a0, sred[(tid + s * 64) * 4 + 0]);
                    ADD2(a1, sred[(tid + s * 64) * 4 + 1]);
                    ADD2(a2, sred[(tid + s * 64) * 4 + 2]);
                    ADD2(a3, sred[(tid + s * 64) * 4 + 3]);
                }
                int j0l = jg1 * 2, bb = bg1 * 4;
                *(unsigned long long *)&sout[(j0l)     * 64 + bb]     = a0;
                *(unsigned long long *)&sout[(j0l)     * 64 + bb + 2] = a1;
                *(unsigned long long *)&sout[(j0l + 1) * 64 + bb]     = a2;
                *(unsigned long long *)&sout[(j0l + 1) * 64 + bb + 2] = a3;
            }
            __syncthreads();
            // epilogue: 512 outputs, 2 per thread
#pragma unroll
            for (int rep = 0; rep < 2; rep++) {
                int e = tid + rep * 256;
                int b = e & 63, jl = e >> 6;
                int J = JA0 + jl;
                float s = sout[jl * 64 + b];
                if (J < 512) {
                    float v = s + g_XrT[xoff + (size_t)J * 64 + b];
                    float r = 1.0f / (1.0f + expf(-v));
                    float h = hst[J * 64 + b];      // staged h, k-index == J
                    __stcg(&g_rhT[J * 64 + b], r * h);
                } else {
                    int jz = J - 512;
                    float v = s + g_XzT[xoff + (size_t)jz * 64 + b];
                    __stcg(&g_z[jz * 64 + b], 1.0f / (1.0f + expf(-v)));
                }
            }
        }
        gbar(target);

        // ================= PHASE 2: hn = rh @ Wh^T -> update =================
        {
#pragma unroll
            for (int half = 0; half < 2; half++) {
                const float *s = g_rhT + half * 16384;
                unsigned db = (unsigned)__cvta_generic_to_shared(hst + half * 16384);
#pragma unroll
                for (int q = 0; q < 16; q++)
                    CP16(db + (tid + q * 256) * 16, s + (tid + q * 256) * 4);
                asm volatile("cp.async.commit_group;");
            }
            unsigned long long a0 = 0, a1 = 0, a2 = 0, a3 = 0;
#pragma unroll
            for (int half = 0; half < 2; half++) {
                if (half == 0) asm volatile("cp.async.wait_group 1;");
                else           asm volatile("cp.async.wait_group 0;");
                __syncthreads();
                const float *hp = hst + half * 16384 + (ks2 * 32) * 64 + bg2 * 4;
                const float *wp = w2d + ((half * 256 + ks2 * 32) * 4 + jg2 * 2) * 2;
#pragma unroll 4
                for (int kk = 0; kk < 32; kk++) {
                    ulonglong2 hv = *(const ulonglong2 *)hp;
                    ulonglong2 wv = *(const ulonglong2 *)wp;
                    FMA2(a0, hv.x, wv.x);
                    FMA2(a1, hv.y, wv.x);
                    FMA2(a2, hv.x, wv.y);
                    FMA2(a3, hv.y, wv.y);
                    hp += 64; wp += 8;
                }
                __syncthreads();
            }
            sred[tid * 4 + 0] = a0; sred[tid * 4 + 1] = a1;
            sred[tid * 4 + 2] = a2; sred[tid * 4 + 3] = a3;
            __syncthreads();
            if (tid < 32) {
#pragma unroll
                for (int s = 1; s < 8; s++) {
                    ADD2(a0, sred[(tid + s * 32) * 4 + 0]);
                    ADD2(a1, sred[(tid + s * 32) * 4 + 1]);
                    ADD2(a2, sred[(tid + s * 32) * 4 + 2]);
                    ADD2(a3, sred[(tid + s * 32) * 4 + 3]);
                }
                int j0l = jg2 * 2, bb = bg2 * 4;
                *(unsigned long long *)&sout[(j0l)     * 64 + bb]     = a0;
                *(unsigned long long *)&sout[(j0l)     * 64 + bb + 2] = a1;
                *(unsigned long long *)&sout[(j0l + 1) * 64 + bb]     = a2;
                *(unsigned long long *)&sout[(j0l + 1) * 64 + bb + 2] = a3;
            }
            __syncthreads();
            // epilogue: 256 outputs, 1 per thread
            {
                int b = tid & 63, jl = tid >> 6;
                int J = JB0 + jl;
                float sh = sout[jl * 64 + b] + g_XhT[xoff + (size_t)J * 64 + b];
                float ht = tanhf(sh);
                float z  = __ldcg(&g_z[J * 64 + b]);
                float h  = __ldcg(&g_hT[J * 64 + b]);
                float hn = h + z * (ht - h);
                __stcg(&g_hT[J * 64 + b], hn);
                if (store_hs)
                    g_HS[((size_t)t * 64 + b) * 512 + J] = hn;
            }
        }
        gbar(target);
    }
}

// ---------------- final FC ----------------
__global__ void fc_kernel(const float *__restrict__ fcW,
                          const float *__restrict__ fcb,
                          float *__restrict__ out)
{
    int b = threadIdx.x >> 1, c = threadIdx.x & 1;
    float s = 0.0f;
    for (int j = 0; j < Hv; j++)
        s = fmaf(g_hT[j * 64 + b], fcW[c * Hv + j], s);
    out[b * 2 + c] = s + fcb[c];
}

// ---------------- launch ----------------
extern "C" void kernel_launch(void* const* d_in, const int* in_sizes, int n_in,
                              void* d_out, int out_size) {
    const int   *tokens = (const int *)d_in[0];
    const float *emb = (const float *)d_in[1];
    const float *Wr0 = (const float *)d_in[2];
    const float *br0 = (const float *)d_in[3];
    const float *Wz0 = (const float *)d_in[4];
    const float *bz0 = (const float *)d_in[5];
    const float *Wh0 = (const float *)d_in[6];
    const float *bh0 = (const float *)d_in[7];
    const float *Wr1 = (const float *)d_in[8];
    const float *br1 = (const float *)d_in[9];
    const float *Wz1 = (const float *)d_in[10];
    const float *bz1 = (const float *)d_in[11];
    const float *Wh1 = (const float *)d_in[12];
    const float *bh1 = (const float *)d_in[13];
    const float *fcW = (const float *)d_in[14];
    const float *fcb = (const float *)d_in[15];
    float *out = (float *)d_out;

    static int smem_set = 0;
    if (!smem_set) {
        cudaFuncSetAttribute(gru_rec_kernel,
                             cudaFuncAttributeMaxDynamicSharedMemorySize,
                             SM_TOT_FLOATS * 4);
        smem_set = 1;
    }

    dim3 gx(512, 24);

    // Layer 0
    xproj_kernel<1><<<gx, 256>>>(emb, tokens, Wr0, Wz0, Wh0, br0, bz0, bh0,
                                 256, 768);
    reset_bar<<<1, 1>>>();
    gru_rec_kernel<<<NCTA, 256, SM_TOT_FLOATS * 4>>>(Wr0, Wz0, Wh0, 256, 768, 1);

    // Layer 1
    xproj_kernel<0><<<gx, 256>>>(nullptr, nullptr, Wr1, Wz1, Wh1, br1, bz1, bh1,
                                 512, 1024);
    reset_bar<<<1, 1>>>();
    gru_rec_kernel<<<NCTA, 256, SM_TOT_FLOATS * 4>>>(Wr1, Wz1, Wh1, 512, 1024, 0);

    // Classifier
    fc_kernel<<<1, 128>>>(fcW, fcb, out);
}

// round 10
// speedup vs baseline: 1.5430x; 1.0945x over previous
#include <cuda_runtime.h>
#include <math.h>

#define Bv 64
#define Tv 1024
#define Hv 512
#define NCTA 128

// ---------------- device scratch ----------------
// X projections stored TRANSPOSED: X?T[t][j][b] = [(t*512 + j)*64 + b]
__device__ __align__(16) float g_XrT[(size_t)Tv * Hv * Bv];
__device__ __align__(16) float g_XzT[(size_t)Tv * Hv * Bv];
__device__ __align__(16) float g_XhT[(size_t)Tv * Hv * Bv];
__device__ __align__(16) float g_HS [(size_t)Tv * Bv * Hv];  // layer-0 outputs [m][j]
__device__ __align__(16) float g_hT [Hv * Bv];               // hidden state [j][b]
__device__ __align__(16) float g_rhT[Hv * Bv];               // r*h [j][b]
__device__ __align__(16) float g_z  [Hv * Bv];               // z gate [j][b]
__device__ unsigned int g_bar;

__global__ void reset_bar() { g_bar = 0u; }

// R7-proven atomic-counter grid barrier.
__device__ __forceinline__ void gbar(unsigned int &target) {
    __syncthreads();
    if (threadIdx.x == 0) {
        __threadfence();
        atomicAdd(&g_bar, 1u);
        target += NCTA;
        while (*(volatile unsigned int *)&g_bar < target) { }
        __threadfence();
    }
    __syncthreads();
}

typedef unsigned long long u64;

// Packed fp32x2 helpers (Blackwell FFMA2 via PTX)
#define FMA2(d, a, b) asm("fma.rn.f32x2 %0, %1, %2, %0;" : "+l"(d) : "l"(a), "l"(b))
#define ADD2(d, a)    asm("add.rn.f32x2 %0, %0, %1;"     : "+l"(d) : "l"(a))
#define DUP2(d, f)    asm("mov.b64 %0, {%1, %1};"        : "=l"(d) : "f"(f))
#define CP16(dst, src) asm volatile("cp.async.cg.shared.global [%0], [%1], 16;" \
                                    :: "r"(dst), "l"(src))

// ---------------- pre-projection GEMM (128x64 tile, 8x4 micro) ----------------
// Writes transposed: j<512 -> g_XrT, j<1024 -> g_XzT, else -> g_XhT.
template <int GATHER>
__global__ void __launch_bounds__(256) xproj_kernel(
    const float *__restrict__ emb, const int *__restrict__ tokens,
    const float *__restrict__ Wr, const float *__restrict__ Wz,
    const float *__restrict__ Wh,
    const float *__restrict__ br, const float *__restrict__ bz,
    const float *__restrict__ bh,
    int K, int ldW)
{
    __shared__ __align__(16) float As[16][132];
    __shared__ __align__(16) float Bs[16][68];
    __shared__ const float *rowp[128];
    __shared__ const float *colp[64];

    const int tid = threadIdx.x;
    const int m0 = blockIdx.x * 128;
    const int j0 = blockIdx.y * 64;

    if (tid < 128) {
        int m = m0 + tid;
        if (GATHER) {
            int b = m & 63, t = m >> 6;
            rowp[tid] = emb + (size_t)tokens[b * Tv + t] * 256;
        } else {
            rowp[tid] = g_HS + (size_t)m * Hv;
        }
    } else if (tid < 192) {
        int j = j0 + tid - 128;
        const float *w;
        if (j < 512)       w = Wr + (size_t)j * ldW;
        else if (j < 1024) w = Wz + (size_t)(j - 512) * ldW;
        else               w = Wh + (size_t)(j - 1024) * ldW;
        colp[tid - 128] = w;
    }
    __syncthreads();

    const int tx = tid & 15, ty = tid >> 4;
    float acc[8][4];
#pragma unroll
    for (int i = 0; i < 8; i++)
#pragma unroll
        for (int j = 0; j < 4; j++) acc[i][j] = 0.0f;

    for (int k0 = 0; k0 < K; k0 += 16) {
#pragma unroll
        for (int i = 0; i < 2; i++) {
            int id = tid + i * 256;
            int kk = id & 3, r = id >> 2;
            float4 v = *(const float4 *)(rowp[r] + k0 + kk * 4);
            As[kk * 4 + 0][r] = v.x; As[kk * 4 + 1][r] = v.y;
            As[kk * 4 + 2][r] = v.z; As[kk * 4 + 3][r] = v.w;
        }
        {
            int kk = tid & 3, jj = tid >> 2;
            float4 v = *(const float4 *)(colp[jj] + k0 + kk * 4);
            Bs[kk * 4 + 0][jj] = v.x; Bs[kk * 4 + 1][jj] = v.y;
            Bs[kk * 4 + 2][jj] = v.z; Bs[kk * 4 + 3][jj] = v.w;
        }
        __syncthreads();
#pragma unroll
        for (int k = 0; k < 16; k++) {
            float a[8], w[4];
            *(float4 *)&a[0] = *(const float4 *)&As[k][ty * 8];
            *(float4 *)&a[4] = *(const float4 *)&As[k][ty * 8 + 4];
            *(float4 *)&w[0] = *(const float4 *)&Bs[k][tx * 4];
#pragma unroll
            for (int i = 0; i < 8; i++)
#pragma unroll
                for (int j = 0; j < 4; j++)
                    acc[i][j] = fmaf(a[i], w[j], acc[i][j]);
        }
        __syncthreads();
    }

    float *dst; const float *bias; int jloc;
    if (j0 < 512)       { dst = g_XrT; bias = br; jloc = j0; }
    else if (j0 < 1024) { dst = g_XzT; bias = bz; jloc = j0 - 512; }
    else                { dst = g_XhT; bias = bh; jloc = j0 - 1024; }

    const int c0 = jloc + tx * 4;
    const int t  = (m0 >> 6) + (ty >> 3);
    const int b0 = (ty & 7) * 8;
    const float bsv[4] = {bias[c0], bias[c0 + 1], bias[c0 + 2], bias[c0 + 3]};
#pragma unroll
    for (int jj = 0; jj < 4; jj++) {
        int jg = c0 + jj;
        float4 lo = make_float4(acc[0][jj] + bsv[jj], acc[1][jj] + bsv[jj],
                                acc[2][jj] + bsv[jj], acc[3][jj] + bsv[jj]);
        float4 hi = make_float4(acc[4][jj] + bsv[jj], acc[5][jj] + bsv[jj],
                                acc[6][jj] + bsv[jj], acc[7][jj] + bsv[jj]);
        size_t o = ((size_t)t * 512 + jg) * 64 + b0;
        *(float4 *)&dst[o]     = lo;
        *(float4 *)&dst[o + 4] = hi;
    }
}

// ---------------- persistent GRU recurrence (2 barriers/step) ----------------
// SMEM layout (float indices):
#define SM_W1   0          /* compact phase-1 weights: 512k x 8 cols  (4096 f) */
#define SM_W2   4096       /* compact phase-2 weights: 512k x 4 cols  (2048 f) */
#define SM_HST  6144       /* staging [k][b], 512 x 64                (32768 f) */
#define SM_SRED 38912      /* reduction: 16 x 260 u64                 (8320 f) */
#define SM_SOUT 47232      /* up to 256 u64                            (512 f) */
#define SM_TOT_FLOATS 47744  /* 190976 bytes */
#define SRED_PITCH 260

__global__ void __launch_bounds__(256) gru_rec_kernel(
    const float *__restrict__ Wr, const float *__restrict__ Wz,
    const float *__restrict__ Wh,
    int D, int ldW, int store_hs)
{
    extern __shared__ __align__(16) float smem[];
    float *w1c = smem + SM_W1;
    float *w2c = smem + SM_W2;
    float *hst = smem + SM_HST;
    u64   *sred = (u64 *)(smem + SM_SRED);
    u64   *sout = (u64 *)(smem + SM_SOUT);

    const int tid = threadIdx.x;
    const int cid = blockIdx.x;
    const int JA0 = cid * 8;   // phase-1 rz-column base (0..1023)
    const int JB0 = cid * 4;   // phase-2 h-column base  (0..511)

    // ---- one-time compact weight preload ----
    for (int e = tid; e < 4096; e += 256) {        // W1c[k*8 + jl]
        int k = e >> 3, jl = e & 7;
        int jg = JA0 + jl;
        const float *row = (jg < 512) ? (Wr + (size_t)jg * ldW)
                                      : (Wz + (size_t)(jg - 512) * ldW);
        w1c[e] = row[D + k];
    }
    for (int e = tid; e < 2048; e += 256) {        // W2c[k*4 + jl]
        int k = e >> 2, jl = e & 3;
        w2c[e] = Wh[(size_t)(JB0 + jl) * ldW + D + k];
    }
    __stcg(&g_hT[cid * 256 + tid], 0.0f);          // h0 = 0
    unsigned int target = 0;
    gbar(target);

    // phase-1 thread roles: ks in [0,16), slab = jg*8+bg handled as (jg,bg)
    const int ks1 = tid >> 4, slab1 = tid & 15;
    const int jg1 = slab1 >> 3, bg1 = slab1 & 7;
    // phase-2 roles: ks in [0,32), bg
    const int ks2 = tid >> 3, bg2 = tid & 7;

    for (int t = 0; t < Tv; t++) {
        const size_t xoff = (size_t)t * 32768;     // t*512*64

        // ================= PHASE 1: rz = h @ W1^T =================
        {
#pragma unroll
            for (int half = 0; half < 2; half++) {
                const float *s = g_hT + half * 16384;
                unsigned db = (unsigned)__cvta_generic_to_shared(hst + half * 16384);
#pragma unroll
                for (int q = 0; q < 16; q++)
                    CP16(db + (tid + q * 256) * 16, s + (tid + q * 256) * 4);
                asm volatile("cp.async.commit_group;");
            }
            u64 a[16];
#pragma unroll
            for (int i = 0; i < 16; i++) a[i] = 0;
#pragma unroll
            for (int half = 0; half < 2; half++) {
                if (half == 0) asm volatile("cp.async.wait_group 1;");
                else           asm volatile("cp.async.wait_group 0;");
                __syncthreads();
                const float *hp = hst + (half * 256 + ks1 * 16) * 64 + bg1 * 8;
                const float *wp = w1c + (half * 256 + ks1 * 16) * 8 + jg1 * 4;
#pragma unroll
                for (int kk = 0; kk < 16; kk++) {
                    ulonglong2 h01 = *(const ulonglong2 *)hp;       // b0..b3
                    ulonglong2 h23 = *(const ulonglong2 *)(hp + 4); // b4..b7
                    float4 wf = *(const float4 *)wp;
                    u64 wd;
                    DUP2(wd, wf.x);
                    FMA2(a[0], h01.x, wd); FMA2(a[1], h01.y, wd);
                    FMA2(a[2], h23.x, wd); FMA2(a[3], h23.y, wd);
                    DUP2(wd, wf.y);
                    FMA2(a[4], h01.x, wd); FMA2(a[5], h01.y, wd);
                    FMA2(a[6], h23.x, wd); FMA2(a[7], h23.y, wd);
                    DUP2(wd, wf.z);
                    FMA2(a[8],  h01.x, wd); FMA2(a[9],  h01.y, wd);
                    FMA2(a[10], h23.x, wd); FMA2(a[11], h23.y, wd);
                    DUP2(wd, wf.w);
                    FMA2(a[12], h01.x, wd); FMA2(a[13], h01.y, wd);
                    FMA2(a[14], h23.x, wd); FMA2(a[15], h23.y, wd);
                    hp += 64; wp += 8;
                }
                __syncthreads();
            }
#pragma unroll
            for (int i = 0; i < 16; i++)
                sred[i * SRED_PITCH + tid] = a[i];
            __syncthreads();
            // 16-way ksplit reduction: slab = tid&15, i = tid>>4
            {
                int slab = tid & 15, i = tid >> 4;
                u64 s = sred[i * SRED_PITCH + slab];
#pragma unroll
                for (int ks = 1; ks < 16; ks++)
                    ADD2(s, sred[i * SRED_PITCH + ks * 16 + slab]);
                sout[slab * 16 + i] = s;
            }
            __syncthreads();
            // epilogue: 512 outputs, 2 per thread
#pragma unroll
            for (int rep = 0; rep < 2; rep++) {
                int e = tid + rep * 256;
                int jl = e >> 6, b = e & 63;
                int jg = jl >> 2, jp = jl & 3;
                int bg = b >> 3, w8 = b & 7, bp = w8 >> 1, ln = w8 & 1;
                float s = ((const float *)&sout[(jg * 8 + bg) * 16 + jp * 4 + bp])[ln];
                int J = JA0 + jl;
                if (J < 512) {
                    float v = s + g_XrT[xoff + (size_t)J * 64 + b];
                    float r = 1.0f / (1.0f + expf(-v));
                    float h = hst[J * 64 + b];      // staged h, k-index == J
                    __stcg(&g_rhT[J * 64 + b], r * h);
                } else {
                    int jz = J - 512;
                    float v = s + g_XzT[xoff + (size_t)jz * 64 + b];
                    __stcg(&g_z[jz * 64 + b], 1.0f / (1.0f + expf(-v)));
                }
            }
        }
        gbar(target);

        // ================= PHASE 2: hn = rh @ Wh^T -> update =================
        {
#pragma unroll
            for (int half = 0; half < 2; half++) {
                const float *s = g_rhT + half * 16384;
                unsigned db = (unsigned)__cvta_generic_to_shared(hst + half * 16384);
#pragma unroll
                for (int q = 0; q < 16; q++)
                    CP16(db + (tid + q * 256) * 16, s + (tid + q * 256) * 4);
                asm volatile("cp.async.commit_group;");
            }
            u64 a[16];
#pragma unroll
            for (int i = 0; i < 16; i++) a[i] = 0;
#pragma unroll
            for (int half = 0; half < 2; half++) {
                if (half == 0) asm volatile("cp.async.wait_group 1;");
                else           asm volatile("cp.async.wait_group 0;");
                __syncthreads();
                const float *hp = hst + (half * 256 + ks2 * 8) * 64 + bg2 * 8;
                const float *wp = w2c + (half * 256 + ks2 * 8) * 4;
#pragma unroll
                for (int kk = 0; kk < 8; kk++) {
                    ulonglong2 h01 = *(const ulonglong2 *)hp;
                    ulonglong2 h23 = *(const ulonglong2 *)(hp + 4);
                    float4 wf = *(const float4 *)wp;
                    u64 wd;
                    DUP2(wd, wf.x);
                    FMA2(a[0], h01.x, wd); FMA2(a[1], h01.y, wd);
                    FMA2(a[2], h23.x, wd); FMA2(a[3], h23.y, wd);
                    DUP2(wd, wf.y);
                    FMA2(a[4], h01.x, wd); FMA2(a[5], h01.y, wd);
                    FMA2(a[6], h23.x, wd); FMA2(a[7], h23.y, wd);
                    DUP2(wd, wf.z);
                    FMA2(a[8],  h01.x, wd); FMA2(a[9],  h01.y, wd);
                    FMA2(a[10], h23.x, wd); FMA2(a[11], h23.y, wd);
                    DUP2(wd, wf.w);
                    FMA2(a[12], h01.x, wd); FMA2(a[13], h01.y, wd);
                    FMA2(a[14], h23.x, wd); FMA2(a[15], h23.y, wd);
                    hp += 64; wp += 4;
                }
                __syncthreads();
            }
#pragma unroll
            for (int i = 0; i < 16; i++)
                sred[i * SRED_PITCH + tid] = a[i];
            __syncthreads();
            // 32-way ksplit reduction: 128 threads, slab = t&7, i = (t>>3)&15
            if (tid < 128) {
                int slab = tid & 7, i = tid >> 3;
                u64 s = sred[i * SRED_PITCH + slab];
#pragma unroll
                for (int ks = 1; ks < 32; ks++)
                    ADD2(s, sred[i * SRED_PITCH + ks * 8 + slab]);
                sout[slab * 16 + i] = s;
            }
            __syncthreads();
            // epilogue: 256 outputs, 1 per thread
            {
                int jl = tid >> 6, b = tid & 63;
                int bg = b >> 3, w8 = b & 7, bp = w8 >> 1, ln = w8 & 1;
                float s = ((const float *)&sout[bg * 16 + jl * 4 + bp])[ln];
                int J = JB0 + jl;
                float sh = s + g_XhT[xoff + (size_t)J * 64 + b];
                float ht = tanhf(sh);
                float z  = __ldcg(&g_z[J * 64 + b]);
                float h  = __ldcg(&g_hT[J * 64 + b]);
                float hn = h + z * (ht - h);
                __stcg(&g_hT[J * 64 + b], hn);
                if (store_hs)
                    g_HS[((size_t)t * 64 + b) * 512 + J] = hn;
            }
        }
        gbar(target);
    }
}

// ---------------- final FC ----------------
__global__ void fc_kernel(const float *__restrict__ fcW,
                          const float *__restrict__ fcb,
                          float *__restrict__ out)
{
    int b = threadIdx.x >> 1, c = threadIdx.x & 1;
    float s = 0.0f;
    for (int j = 0; j < Hv; j++)
        s = fmaf(g_hT[j * 64 + b], fcW[c * Hv + j], s);
    out[b * 2 + c] = s + fcb[c];
}

// ---------------- launch ----------------
extern "C" void kernel_launch(void* const* d_in, const int* in_sizes, int n_in,
                              void* d_out, int out_size) {
    const int   *tokens = (const int *)d_in[0];
    const float *emb = (const float *)d_in[1];
    const float *Wr0 = (const float *)d_in[2];
    const float *br0 = (const float *)d_in[3];
    const float *Wz0 = (const float *)d_in[4];
    const float *bz0 = (const float *)d_in[5];
    const float *Wh0 = (const float *)d_in[6];
    const float *bh0 = (const float *)d_in[7];
    const float *Wr1 = (const float *)d_in[8];
    const float *br1 = (const float *)d_in[9];
    const float *Wz1 = (const float *)d_in[10];
    const float *bz1 = (const float *)d_in[11];
    const float *Wh1 = (const float *)d_in[12];
    const float *bh1 = (const float *)d_in[13];
    const float *fcW = (const float *)d_in[14];
    const float *fcb = (const float *)d_in[15];
    float *out = (float *)d_out;

    static int smem_set = 0;
    if (!smem_set) {
        cudaFuncSetAttribute(gru_rec_kernel,
                             cudaFuncAttributeMaxDynamicSharedMemorySize,
                             SM_TOT_FLOATS * 4);
        smem_set = 1;
    }

    dim3 gx(512, 24);

    // Layer 0
    xproj_kernel<1><<<gx, 256>>>(emb, tokens, Wr0, Wz0, Wh0, br0, bz0, bh0,
                                 256, 768);
    reset_bar<<<1, 1>>>();
    gru_rec_kernel<<<NCTA, 256, SM_TOT_FLOATS * 4>>>(Wr0, Wz0, Wh0, 256, 768, 1);

    // Layer 1
    xproj_kernel<0><<<gx, 256>>>(nullptr, nullptr, Wr1, Wz1, Wh1, br1, bz1, bh1,
                                 512, 1024);
    reset_bar<<<1, 1>>>();
    gru_rec_kernel<<<NCTA, 256, SM_TOT_FLOATS * 4>>>(Wr1, Wz1, Wh1, 512, 1024, 0);

    // Classifier
    fc_kernel<<<1, 128>>>(fcW, fcb, out);
}

// round 11
// speedup vs baseline: 1.7060x; 1.1056x over previous
#include <cuda_runtime.h>
#include <math.h>

#define Bv 64
#define Tv 1024
#define Hv 512
#define NCTA 128

// ---------------- device scratch ----------------
// X projections stored TRANSPOSED: X?T[t][j][b] = [(t*512 + j)*64 + b]
__device__ __align__(16) float g_XrT[(size_t)Tv * Hv * Bv];
__device__ __align__(16) float g_XzT[(size_t)Tv * Hv * Bv];
__device__ __align__(16) float g_XhT[(size_t)Tv * Hv * Bv];
__device__ __align__(16) float g_HS [(size_t)Tv * Bv * Hv];  // layer-0 outputs [m][j]
__device__ __align__(16) float g_hT [Hv * Bv];               // hidden state [j][b]
__device__ __align__(16) float g_rhT[Hv * Bv];               // r*h [j][b]
__device__ __align__(16) float g_z  [Hv * Bv];               // z gate [j][b]
__device__ unsigned int g_bar;

__global__ void reset_bar() { g_bar = 0u; }

// R7-proven atomic-counter grid barrier.
__device__ __forceinline__ void gbar(unsigned int &target) {
    __syncthreads();
    if (threadIdx.x == 0) {
        __threadfence();
        atomicAdd(&g_bar, 1u);
        target += NCTA;
        while (*(volatile unsigned int *)&g_bar < target) { }
        __threadfence();
    }
    __syncthreads();
}

typedef unsigned long long u64;

// Packed fp32x2 helpers (Blackwell FFMA2 via PTX)
#define FMA2(d, a, b) asm("fma.rn.f32x2 %0, %1, %2, %0;" : "+l"(d) : "l"(a), "l"(b))
#define ADD2(d, a)    asm("add.rn.f32x2 %0, %0, %1;"     : "+l"(d) : "l"(a))
#define DUP2(d, f)    asm("mov.b64 %0, {%1, %1};"        : "=l"(d) : "f"(f))
#define CP16(dst, src) asm volatile("cp.async.cg.shared.global [%0], [%1], 16;" \
                                    :: "r"(dst), "l"(src))

// ---------------- pre-projection GEMM (128x64 tile, 8x4 micro) ----------------
template <int GATHER>
__global__ void __launch_bounds__(256) xproj_kernel(
    const float *__restrict__ emb, const int *__restrict__ tokens,
    const float *__restrict__ Wr, const float *__restrict__ Wz,
    const float *__restrict__ Wh,
    const float *__restrict__ br, const float *__restrict__ bz,
    const float *__restrict__ bh,
    int K, int ldW)
{
    __shared__ __align__(16) float As[16][132];
    __shared__ __align__(16) float Bs[16][68];
    __shared__ const float *rowp[128];
    __shared__ const float *colp[64];

    const int tid = threadIdx.x;
    const int m0 = blockIdx.x * 128;
    const int j0 = blockIdx.y * 64;

    if (tid < 128) {
        int m = m0 + tid;
        if (GATHER) {
            int b = m & 63, t = m >> 6;
            rowp[tid] = emb + (size_t)tokens[b * Tv + t] * 256;
        } else {
            rowp[tid] = g_HS + (size_t)m * Hv;
        }
    } else if (tid < 192) {
        int j = j0 + tid - 128;
        const float *w;
        if (j < 512)       w = Wr + (size_t)j * ldW;
        else if (j < 1024) w = Wz + (size_t)(j - 512) * ldW;
        else               w = Wh + (size_t)(j - 1024) * ldW;
        colp[tid - 128] = w;
    }
    __syncthreads();

    const int tx = tid & 15, ty = tid >> 4;
    float acc[8][4];
#pragma unroll
    for (int i = 0; i < 8; i++)
#pragma unroll
        for (int j = 0; j < 4; j++) acc[i][j] = 0.0f;

    for (int k0 = 0; k0 < K; k0 += 16) {
#pragma unroll
        for (int i = 0; i < 2; i++) {
            int id = tid + i * 256;
            int kk = id & 3, r = id >> 2;
            float4 v = *(const float4 *)(rowp[r] + k0 + kk * 4);
            As[kk * 4 + 0][r] = v.x; As[kk * 4 + 1][r] = v.y;
            As[kk * 4 + 2][r] = v.z; As[kk * 4 + 3][r] = v.w;
        }
        {
            int kk = tid & 3, jj = tid >> 2;
            float4 v = *(const float4 *)(colp[jj] + k0 + kk * 4);
            Bs[kk * 4 + 0][jj] = v.x; Bs[kk * 4 + 1][jj] = v.y;
            Bs[kk * 4 + 2][jj] = v.z; Bs[kk * 4 + 3][jj] = v.w;
        }
        __syncthreads();
#pragma unroll
        for (int k = 0; k < 16; k++) {
            float a[8], w[4];
            *(float4 *)&a[0] = *(const float4 *)&As[k][ty * 8];
            *(float4 *)&a[4] = *(const float4 *)&As[k][ty * 8 + 4];
            *(float4 *)&w[0] = *(const float4 *)&Bs[k][tx * 4];
#pragma unroll
            for (int i = 0; i < 8; i++)
#pragma unroll
                for (int j = 0; j < 4; j++)
                    acc[i][j] = fmaf(a[i], w[j], acc[i][j]);
        }
        __syncthreads();
    }

    float *dst; const float *bias; int jloc;
    if (j0 < 512)       { dst = g_XrT; bias = br; jloc = j0; }
    else if (j0 < 1024) { dst = g_XzT; bias = bz; jloc = j0 - 512; }
    else                { dst = g_XhT; bias = bh; jloc = j0 - 1024; }

    const int c0 = jloc + tx * 4;
    const int t  = (m0 >> 6) + (ty >> 3);
    const int b0 = (ty & 7) * 8;
    const float bsv[4] = {bias[c0], bias[c0 + 1], bias[c0 + 2], bias[c0 + 3]};
#pragma unroll
    for (int jj = 0; jj < 4; jj++) {
        int jg = c0 + jj;
        float4 lo = make_float4(acc[0][jj] + bsv[jj], acc[1][jj] + bsv[jj],
                                acc[2][jj] + bsv[jj], acc[3][jj] + bsv[jj]);
        float4 hi = make_float4(acc[4][jj] + bsv[jj], acc[5][jj] + bsv[jj],
                                acc[6][jj] + bsv[jj], acc[7][jj] + bsv[jj]);
        size_t o = ((size_t)t * 512 + jg) * 64 + b0;
        *(float4 *)&dst[o]     = lo;
        *(float4 *)&dst[o + 4] = hi;
    }
}

// ---------------- persistent GRU recurrence (2D decomposition) ----------------
// 128 CTAs = 32 colgroups x 4 batchgroups. CTA (cg, bg) owns batches bg*16..+16.
// Phase 1: cols cg*32..+32 of the 1024 rz outputs, full k in-CTA (16-way strided ksplit).
// Phase 2: cols cg*16..+16 of the 512 h~ outputs (32-way strided ksplit).
// Per-CTA staging = only its 16 batches (32 KB vs 128 KB) -> 4x less L2 traffic.
// SMEM float offsets:
#define SM_W1    0          /* [k][32] pad->stride 36 : 512*36 = 18432 f */
#define SM_W2    18432      /* [k][16] pad->stride 20 : 512*20 = 10240 f */
#define SM_HST   28672      /* [k][16] pad->stride 20 : 10240 f */
#define SM_SRED  38912      /* 16 x 260 u64 = 8320 f */
#define SM_SOUT  47232      /* 256 u64 = 512 f */
#define SM_HSAVE 47744      /* 256 f */
#define SM_TOT_FLOATS 48000 /* 192000 bytes */
#define SRED_PITCH 260

__global__ void __launch_bounds__(256) gru_rec_kernel(
    const float *__restrict__ Wr, const float *__restrict__ Wz,
    const float *__restrict__ Wh,
    int D, int ldW, int store_hs)
{
    extern __shared__ __align__(16) float smem[];
    float *w1   = smem + SM_W1;
    float *w2   = smem + SM_W2;
    float *hst  = smem + SM_HST;
    u64   *sred = (u64 *)(smem + SM_SRED);
    u64   *sout = (u64 *)(smem + SM_SOUT);
    float *hsave = smem + SM_HSAVE;

    const int tid = threadIdx.x;
    const int cid = blockIdx.x;
    const int cg  = cid >> 2;          // 0..31
    const int bg  = cid & 3;           // 0..3
    const int JA0 = cg * 32;           // phase-1 col base (0..1023)
    const int JB0 = cg * 16;           // phase-2 col base (0..511)
    const int B0  = bg * 16;           // batch base

    // ---- one-time weight preload (compact, padded rows) ----
    for (int e = tid; e < 32 * 512; e += 256) {       // col = e>>9, k = e&511
        int k = e & 511, col = e >> 9;
        int jg = JA0 + col;
        const float *row = (jg < 512) ? (Wr + (size_t)jg * ldW)
                                      : (Wz + (size_t)(jg - 512) * ldW);
        w1[k * 36 + col] = row[D + k];
    }
    for (int e = tid; e < 16 * 512; e += 256) {
        int k = e & 511, col = e >> 9;
        w2[k * 20 + col] = Wh[(size_t)(JB0 + col) * ldW + D + k];
    }
    __stcg(&g_hT[cid * 256 + tid], 0.0f);             // h0 = 0
    unsigned int target = 0;
    gbar(target);

    // phase-1 roles: ks1 in [0,16), slab = colsub1(8) x bsub1(2)
    const int ks1 = tid >> 4, slab1 = tid & 15;
    const int colsub1 = slab1 >> 1, bsub1 = slab1 & 1;
    // phase-2 roles: ks2 in [0,32), slab = colsub2(4) x bsub2(2)
    const int ks2 = tid >> 3, slab2 = tid & 7;
    const int colsub2 = slab2 >> 1, bsub2 = slab2 & 1;

    for (int t = 0; t < Tv; t++) {
        const size_t xoff = (size_t)t * 32768;        // t*512*64

        // ================= PHASE 1: rz = h @ W1^T =================
        {
            // stage h[all k][own 16 batches] : 512 rows x 64B
#pragma unroll
            for (int it = 0; it < 8; it++) {
                int q = tid + it * 256;               // 0..2047
                int row = q >> 2, quad = q & 3;
                CP16((unsigned)__cvta_generic_to_shared(hst + row * 20 + quad * 4),
                     g_hT + row * 64 + B0 + quad * 4);
            }
            asm volatile("cp.async.commit_group;");
            asm volatile("cp.async.wait_group 0;");
            __syncthreads();

            u64 a[16];
#pragma unroll
            for (int i = 0; i < 16; i++) a[i] = 0;
            {
                const float *hp = hst + ks1 * 20 + bsub1 * 8;
                const float *wp = w1 + ks1 * 36 + colsub1 * 4;
#pragma unroll 4
                for (int i = 0; i < 32; i++) {        // k = i*16 + ks1
                    ulonglong2 h01 = *(const ulonglong2 *)hp;
                    ulonglong2 h23 = *(const ulonglong2 *)(hp + 4);
                    float4 wf = *(const float4 *)wp;
                    u64 wd;
                    DUP2(wd, wf.x);
                    FMA2(a[0], h01.x, wd); FMA2(a[1], h01.y, wd);
                    FMA2(a[2], h23.x, wd); FMA2(a[3], h23.y, wd);
                    DUP2(wd, wf.y);
                    FMA2(a[4], h01.x, wd); FMA2(a[5], h01.y, wd);
                    FMA2(a[6], h23.x, wd); FMA2(a[7], h23.y, wd);
                    DUP2(wd, wf.z);
                    FMA2(a[8],  h01.x, wd); FMA2(a[9],  h01.y, wd);
                    FMA2(a[10], h23.x, wd); FMA2(a[11], h23.y, wd);
                    DUP2(wd, wf.w);
                    FMA2(a[12], h01.x, wd); FMA2(a[13], h01.y, wd);
                    FMA2(a[14], h23.x, wd); FMA2(a[15], h23.y, wd);
                    hp += 320; wp += 576;
                }
            }
#pragma unroll
            for (int i = 0; i < 16; i++)
                sred[i * SRED_PITCH + tid] = a[i];
            __syncthreads();
            {   // 16-way ksplit reduction
                int slab = tid & 15, ii = tid >> 4;
                u64 s = sred[ii * SRED_PITCH + slab];
#pragma unroll
                for (int ks = 1; ks < 16; ks++)
                    ADD2(s, sred[ii * SRED_PITCH + ks * 16 + slab]);
                sout[slab * 16 + ii] = s;
            }
            // save h needed by phase-2 epilogue before hst is re-staged
            hsave[tid] = hst[(JB0 + (tid >> 4)) * 20 + (tid & 15)];
            __syncthreads();
            // epilogue: 512 outputs, 2 per thread
#pragma unroll
            for (int rep = 0; rep < 2; rep++) {
                int e = tid + rep * 256;
                int jl = e >> 4, bb = e & 15;
                int slab = ((jl >> 2) << 1) | (bb >> 3);
                int ii = (jl & 3) * 4 + ((bb & 7) >> 1);
                float val = ((const float *)sout)[(slab * 16 + ii) * 2 + (bb & 1)];
                int J = JA0 + jl, bglob = B0 + bb;
                if (J < 512) {
                    float v = val + g_XrT[xoff + (size_t)J * 64 + bglob];
                    float r = 1.0f / (1.0f + expf(-v));
                    __stcg(&g_rhT[J * 64 + bglob], r * hst[J * 20 + bb]);
                } else {
                    float v = val + g_XzT[xoff + (size_t)(J - 512) * 64 + bglob];
                    __stcg(&g_z[(J - 512) * 64 + bglob], 1.0f / (1.0f + expf(-v)));
                }
            }
        }
        gbar(target);

        // ================= PHASE 2: hn = rh @ Wh^T -> update =================
        {
#pragma unroll
            for (int it = 0; it < 8; it++) {
                int q = tid + it * 256;
                int row = q >> 2, quad = q & 3;
                CP16((unsigned)__cvta_generic_to_shared(hst + row * 20 + quad * 4),
                     g_rhT + row * 64 + B0 + quad * 4);
            }
            asm volatile("cp.async.commit_group;");
            asm volatile("cp.async.wait_group 0;");
            __syncthreads();

            u64 a[16];
#pragma unroll
            for (int i = 0; i < 16; i++) a[i] = 0;
            {
                const float *hp = hst + ks2 * 20 + bsub2 * 8;
                const float *wp = w2 + ks2 * 20 + colsub2 * 4;
#pragma unroll 4
                for (int i = 0; i < 16; i++) {        // k = i*32 + ks2
                    ulonglong2 h01 = *(const ulonglong2 *)hp;
                    ulonglong2 h23 = *(const ulonglong2 *)(hp + 4);
                    float4 wf = *(const float4 *)wp;
                    u64 wd;
                    DUP2(wd, wf.x);
                    FMA2(a[0], h01.x, wd); FMA2(a[1], h01.y, wd);
                    FMA2(a[2], h23.x, wd); FMA2(a[3], h23.y, wd);
                    DUP2(wd, wf.y);
                    FMA2(a[4], h01.x, wd); FMA2(a[5], h01.y, wd);
                    FMA2(a[6], h23.x, wd); FMA2(a[7], h23.y, wd);
                    DUP2(wd, wf.z);
                    FMA2(a[8],  h01.x, wd); FMA2(a[9],  h01.y, wd);
                    FMA2(a[10], h23.x, wd); FMA2(a[11], h23.y, wd);
                    DUP2(wd, wf.w);
                    FMA2(a[12], h01.x, wd); FMA2(a[13], h01.y, wd);
                    FMA2(a[14], h23.x, wd); FMA2(a[15], h23.y, wd);
                    hp += 640; wp += 640;
                }
            }
#pragma unroll
            for (int i = 0; i < 16; i++)
                sred[i * SRED_PITCH + tid] = a[i];
            __syncthreads();
            if (tid < 128) {   // 32-way ksplit reduction
                int slab = tid & 7, ii = tid >> 3;
                u64 s = sred[ii * SRED_PITCH + slab];
#pragma unroll
                for (int ks = 1; ks < 32; ks++)
                    ADD2(s, sred[ii * SRED_PITCH + ks * 8 + slab]);
                sout[slab * 16 + ii] = s;
            }
            __syncthreads();
            // epilogue: 256 outputs, 1 per thread (jl fastest for coalesced HS)
            {
                int jl = tid & 15, bb = tid >> 4;
                int slab = ((jl >> 2) << 1) | (bb >> 3);
                int ii = (jl & 3) * 4 + ((bb & 7) >> 1);
                float val = ((const float *)sout)[(slab * 16 + ii) * 2 + (bb & 1)];
                int J = JB0 + jl, bglob = B0 + bb;
                float sh = val + g_XhT[xoff + (size_t)J * 64 + bglob];
                float ht = tanhf(sh);
                float z  = __ldcg(&g_z[J * 64 + bglob]);
                float h  = hsave[bb * 16 + jl];
                // hsave was stored as [jl2*16 + b] with jl2 = tid>>4; re-index:
                h = hsave[jl * 16 + bb];
                float hn = h + z * (ht - h);
                __stcg(&g_hT[J * 64 + bglob], hn);
                if (store_hs)
                    g_HS[((size_t)t * 64 + bglob) * 512 + J] = hn;
            }
        }
        gbar(target);
    }
}

// ---------------- final FC ----------------
__global__ void fc_kernel(const float *__restrict__ fcW,
                          const float *__restrict__ fcb,
                          float *__restrict__ out)
{
    int b = threadIdx.x >> 1, c = threadIdx.x & 1;
    float s = 0.0f;
    for (int j = 0; j < Hv; j++)
        s = fmaf(g_hT[j * 64 + b], fcW[c * Hv + j], s);
    out[b * 2 + c] = s + fcb[c];
}

// ---------------- launch ----------------
extern "C" void kernel_launch(void* const* d_in, const int* in_sizes, int n_in,
                              void* d_out, int out_size) {
    const int   *tokens = (const int *)d_in[0];
    const float *emb = (const float *)d_in[1];
    const float *Wr0 = (const float *)d_in[2];
    const float *br0 = (const float *)d_in[3];
    const float *Wz0 = (const float *)d_in[4];
    const float *bz0 = (const float *)d_in[5];
    const float *Wh0 = (const float *)d_in[6];
    const float *bh0 = (const float *)d_in[7];
    const float *Wr1 = (const float *)d_in[8];
    const float *br1 = (const float *)d_in[9];
    const float *Wz1 = (const float *)d_in[10];
    const float *bz1 = (const float *)d_in[11];
    const float *Wh1 = (const float *)d_in[12];
    const float *bh1 = (const float *)d_in[13];
    const float *fcW = (const float *)d_in[14];
    const float *fcb = (const float *)d_in[15];
    float *out = (float *)d_out;

    static int smem_set = 0;
    if (!smem_set) {
        cudaFuncSetAttribute(gru_rec_kernel,
                             cudaFuncAttributeMaxDynamicSharedMemorySize,
                             SM_TOT_FLOATS * 4);
        smem_set = 1;
    }

    dim3 gx(512, 24);

    // Layer 0
    xproj_kernel<1><<<gx, 256>>>(emb, tokens, Wr0, Wz0, Wh0, br0, bz0, bh0,
                                 256, 768);
    reset_bar<<<1, 1>>>();
    gru_rec_kernel<<<NCTA, 256, SM_TOT_FLOATS * 4>>>(Wr0, Wz0, Wh0, 256, 768, 1);

    // Layer 1
    xproj_kernel<0><<<gx, 256>>>(nullptr, nullptr, Wr1, Wz1, Wh1, br1, bz1, bh1,
                                 512, 1024);
    reset_bar<<<1, 1>>>();
    gru_rec_kernel<<<NCTA, 256, SM_TOT_FLOATS * 4>>>(Wr1, Wz1, Wh1, 512, 1024, 0);

    // Classifier
    fc_kernel<<<1, 128>>>(fcW, fcb, out);
}